// round 6
// baseline (speedup 1.0000x reference)
#include <cuda_runtime.h>
#include <cstddef>

// Problem constants
constexpr int B_   = 64;
constexpr int T_   = 2048;
constexpr int H_   = 100;
constexpr int IN_  = 10;
constexpr int OUT_ = 10;
constexpr int L_   = 5;
constexpr int M_   = B_ * T_;          // 131072 rows
constexpr int BUF_ELEMS = M_ * H_;     // 13,107,200 floats = 52.4 MB

// Scratch ping-pong buffers (device globals: no allocation anywhere)
__device__ float g_bufA[BUF_ELEMS];
__device__ float g_bufB[BUF_ELEMS];

// ---------------------------------------------------------------------------
// Packed f32x2 helpers (sm_103a FFMA2 — only reachable via PTX fma.rn.f32x2)
// ---------------------------------------------------------------------------
__device__ __forceinline__ unsigned long long ffma2(unsigned long long a,
                                                    unsigned long long b,
                                                    unsigned long long c) {
    unsigned long long d;
    asm("fma.rn.f32x2 %0, %1, %2, %3;" : "=l"(d) : "l"(a), "l"(b), "l"(c));
    return d;
}
__device__ __forceinline__ unsigned long long pack2(float lo, float hi) {
    unsigned long long r;
    asm("mov.b64 %0, {%1, %2};" : "=l"(r) : "f"(lo), "f"(hi));
    return r;
}
__device__ __forceinline__ float lo2(unsigned long long v) {
    return __uint_as_float((unsigned)(v & 0xFFFFFFFFull));
}
__device__ __forceinline__ float hi2(unsigned long long v) {
    return __uint_as_float((unsigned)(v >> 32));
}

// ---------------------------------------------------------------------------
// Fast, overflow-safe tanh:  tanh(x) = sign(x) * (1 - e) / (1 + e),
// e = exp(-2|x|) in (0,1]  -> no overflow, no NaN, ~1e-6 accurate.
// ---------------------------------------------------------------------------
__device__ __forceinline__ float fast_tanh(float x) {
    float e = __expf(-2.0f * fabsf(x));
    float t = __fdividef(1.0f - e, 1.0f + e);
    return copysignf(t, x);
}

// ---------------------------------------------------------------------------
// GEMM:  C[m][c] = sum_k A[m][k] * W[c][k] + b1[c] + b2[c]
//   A: [M_, DIN], W: [H_, DIN], C: [M_, H_]
// Block: 256 threads = (c in [0,128), g in {0,1}); 16-row tiles, thread does
// 8 rows for its column. W cached in smem once per block. A-tile reads are
// warp-uniform broadcasts.
// ---------------------------------------------------------------------------
template <int DIN>
__global__ void __launch_bounds__(256)
gemm_k(const float* __restrict__ A, const float* __restrict__ W,
       const float* __restrict__ b1, const float* __restrict__ b2,
       float* __restrict__ C)
{
    __shared__ __align__(16) float Ws[H_ * DIN];
    __shared__ __align__(16) float As[16 * DIN];

    for (int i = threadIdx.x; i < H_ * DIN; i += 256) Ws[i] = W[i];

    const int c = threadIdx.x & 127;   // column (active if < 100)
    const int g = threadIdx.x >> 7;    // row parity 0/1
    const bool act = (c < H_);
    const float bias = act ? (b1[c] + b2[c]) : 0.0f;

    const int tilesTotal = M_ / 16;
    for (int tile = blockIdx.x; tile < tilesTotal; tile += gridDim.x) {
        __syncthreads();  // previous tile's readers done before overwrite
        const float* Arow = A + (size_t)tile * 16 * DIN;
        for (int i = threadIdx.x; i < 16 * DIN; i += 256) As[i] = Arow[i];
        __syncthreads();

        if (act) {
            float acc[8];
            #pragma unroll
            for (int r = 0; r < 8; r++) acc[r] = bias;

            if constexpr (DIN % 4 == 0) {
                const float4* W4 = reinterpret_cast<const float4*>(&Ws[c * DIN]);
                #pragma unroll 5
                for (int k4 = 0; k4 < DIN / 4; k4++) {
                    const float4 wv = W4[k4];
                    #pragma unroll
                    for (int r = 0; r < 8; r++) {
                        const float4 av = *reinterpret_cast<const float4*>(
                            &As[(g + 2 * r) * DIN + 4 * k4]);
                        acc[r] += wv.x * av.x;
                        acc[r] += wv.y * av.y;
                        acc[r] += wv.z * av.z;
                        acc[r] += wv.w * av.w;
                    }
                }
            } else {
                #pragma unroll
                for (int k = 0; k < DIN; k++) {
                    const float wv = Ws[c * DIN + k];
                    #pragma unroll
                    for (int r = 0; r < 8; r++)
                        acc[r] += wv * As[(g + 2 * r) * DIN + k];
                }
            }
            #pragma unroll
            for (int r = 0; r < 8; r++) {
                const int m = tile * 16 + g + 2 * r;
                C[(size_t)m * H_ + c] = acc[r];
            }
        }
    }
}

// ---------------------------------------------------------------------------
// Recurrent scan for one layer, one CTA per batch element, in-place on xp.
//   xp[b][t][:] holds (input contribution + biases); replaced by h_t.
// Thread j owns neuron j; its 100 W_hh weights live in 50 PACKED f32x2
// registers (W_hh rows are 400 B = 16B-aligned -> direct ulonglong2 loads,
// zero pack instructions). h double-buffered in smem, read as ulonglong2
// broadcasts. Per step per thread: 25 LDS.128 + 50 FFMA2 + ~10 overhead.
// xp prefetched 2 steps ahead. Writes final h (t=T-1) to hfin[b][:].
// ---------------------------------------------------------------------------
__global__ void __launch_bounds__(128)
scan_k(float* __restrict__ xp, const float* __restrict__ Whh,
       const float* __restrict__ h0, float* __restrict__ hfin)
{
    const int b = blockIdx.x;
    const int j = threadIdx.x;
    const bool act = (j < H_);

    __shared__ __align__(16) float h_s[2][104];   // 416 B per buf: both 16B-aligned

    // Packed weights: 50 x f32x2 in registers
    unsigned long long w2[H_ / 2];
    if (act) {
        const ulonglong2* Wp = reinterpret_cast<const ulonglong2*>(Whh + (size_t)j * H_);
        #pragma unroll
        for (int i = 0; i < H_ / 4; i++) {          // 25 x 16B loads
            const ulonglong2 v = Wp[i];
            w2[2 * i + 0] = v.x;
            w2[2 * i + 1] = v.y;
        }
        h_s[0][j] = h0[b * H_ + j];
    } else {
        #pragma unroll
        for (int i = 0; i < H_ / 2; i++) w2[i] = 0ull;
    }
    if (j < 4) { h_s[0][H_ + j] = 0.0f; h_s[1][H_ + j] = 0.0f; }
    __syncthreads();

    float* row = xp + (size_t)b * T_ * H_;

    float xa = act ? row[j] : 0.0f;
    float xb = act ? row[H_ + j] : 0.0f;

    int cur = 0;
    float th = 0.0f;

    for (int t = 0; t < T_; t++) {
        unsigned long long acc0 = pack2(xa, 0.0f);
        unsigned long long acc1 = 0ull, acc2 = 0ull, acc3 = 0ull;
        xa = xb;
        if (act && (t + 2 < T_)) xb = row[(t + 2) * H_ + j];

        const ulonglong2* h2 = reinterpret_cast<const ulonglong2*>(h_s[cur]);
        #pragma unroll
        for (int k4 = 0; k4 < H_ / 4; k4++) {       // 25 broadcast LDS.128
            const ulonglong2 hv = h2[k4];
            if ((k4 & 1) == 0) {
                acc0 = ffma2(w2[2 * k4 + 0], hv.x, acc0);
                acc1 = ffma2(w2[2 * k4 + 1], hv.y, acc1);
            } else {
                acc2 = ffma2(w2[2 * k4 + 0], hv.x, acc2);
                acc3 = ffma2(w2[2 * k4 + 1], hv.y, acc3);
            }
        }
        const float s = ((lo2(acc0) + hi2(acc0)) + (lo2(acc1) + hi2(acc1)))
                      + ((lo2(acc2) + hi2(acc2)) + (lo2(acc3) + hi2(acc3)));
        th = fast_tanh(s);

        if (act) {
            h_s[cur ^ 1][j] = th;
            row[t * H_ + j] = th;        // layer output, in place
        }
        __syncthreads();
        cur ^= 1;
    }

    if (act) hfin[b * H_ + j] = th;
}

// ---------------------------------------------------------------------------
// Output projection: y[m][o] = sum_k A[m][k] * Wout[o][k] + bout[o]
// Block 256 = 16 rows x 16 cols (o < 10 active). Memory-bound (52 MB read).
// ---------------------------------------------------------------------------
__global__ void __launch_bounds__(256)
proj_k(const float* __restrict__ A, const float* __restrict__ Wout,
       const float* __restrict__ bout, float* __restrict__ y)
{
    __shared__ __align__(16) float Ws[OUT_ * H_];
    __shared__ float bs[OUT_];
    __shared__ __align__(16) float As[16 * H_];

    for (int i = threadIdx.x; i < OUT_ * H_; i += 256) Ws[i] = Wout[i];
    if (threadIdx.x < OUT_) bs[threadIdx.x] = bout[threadIdx.x];

    const int o  = threadIdx.x & 15;
    const int mi = threadIdx.x >> 4;

    const int tilesTotal = M_ / 16;
    for (int tile = blockIdx.x; tile < tilesTotal; tile += gridDim.x) {
        __syncthreads();
        const float* Arow = A + (size_t)tile * 16 * H_;
        for (int i = threadIdx.x; i < 16 * H_; i += 256) As[i] = Arow[i];
        __syncthreads();

        if (o < OUT_) {
            float acc = bs[o];
            #pragma unroll 4
            for (int k = 0; k < H_; k++)
                acc += As[mi * H_ + k] * Ws[o * H_ + k];
            y[(size_t)(tile * 16 + mi) * OUT_ + o] = acc;
        }
    }
}

// ---------------------------------------------------------------------------
// kernel_launch: 11 kernel launches, graph-capturable, no allocations.
// Input order (metadata): x, hidden_prev, W_ih0, W_ih, W_hh, b_ih, b_hh,
//                         W_out, b_out
// Output: concat( y [B,T,OUT] , h_finals [L,B,H] )
// ---------------------------------------------------------------------------
extern "C" void kernel_launch(void* const* d_in, const int* in_sizes, int n_in,
                              void* d_out, int out_size)
{
    const float* x           = (const float*)d_in[0];
    const float* hidden_prev = (const float*)d_in[1];
    const float* W_ih0       = (const float*)d_in[2];
    const float* W_ih        = (const float*)d_in[3];
    const float* W_hh        = (const float*)d_in[4];
    const float* b_ih        = (const float*)d_in[5];
    const float* b_hh        = (const float*)d_in[6];
    const float* W_out       = (const float*)d_in[7];
    const float* b_out       = (const float*)d_in[8];

    float* out  = (float*)d_out;
    float* y    = out;
    float* hfin = out + (size_t)M_ * OUT_;

    float *bufA, *bufB;
    cudaGetSymbolAddress((void**)&bufA, g_bufA);
    cudaGetSymbolAddress((void**)&bufB, g_bufB);

    // Layer 0: input GEMM (DIN=10) + scan (in place on bufA)
    gemm_k<IN_><<<1024, 256>>>(x, W_ih0, b_ih, b_hh, bufA);
    scan_k<<<B_, 128>>>(bufA, W_hh, hidden_prev, hfin);

    // Layers 1..4: GEMM (DIN=100) into the other buffer, scan in place
    float* src = bufA;
    float* dst = bufB;
    for (int l = 1; l < L_; l++) {
        gemm_k<H_><<<1024, 256>>>(src,
                                  W_ih + (size_t)(l - 1) * H_ * H_,
                                  b_ih + (size_t)l * H_,
                                  b_hh + (size_t)l * H_,
                                  dst);
        scan_k<<<B_, 128>>>(dst,
                            W_hh + (size_t)l * H_ * H_,
                            hidden_prev + (size_t)l * B_ * H_,
                            hfin + (size_t)l * B_ * H_);
        float* tmp = src; src = dst; dst = tmp;
    }

    // Output projection from the last layer's output (src after final swap)
    proj_k<<<512, 256>>>(src, W_out, b_out, y);
}

// round 9
// speedup vs baseline: 1.5449x; 1.5449x over previous
#include <cuda_runtime.h>
#include <cstddef>

using ull = unsigned long long;

// Problem constants
constexpr int B_   = 64;
constexpr int T_   = 2048;
constexpr int H_   = 100;
constexpr int IN_  = 10;
constexpr int OUT_ = 10;
constexpr int L_   = 5;
constexpr int M_   = B_ * T_;          // 131072 rows
constexpr int BUF_ELEMS = M_ * H_;     // 52.4 MB

constexpr int TC_    = 64;             // timesteps per chunk
constexpr int NC_    = T_ / TC_;       // 32 chunks
constexpr int NSTAGE = NC_ + L_ - 1;   // 36 wavefront stages

// Scratch (device globals: no allocation anywhere)
__device__ float g_bufA[BUF_ELEMS];    // output of layers 0,2,4
__device__ float g_bufB[BUF_ELEMS];    // output of layers 1,3
__device__ float g_hst[L_ * B_ * H_];  // per-layer hidden-state carry

// ---------------------------------------------------------------------------
// Packed f32x2 helpers (sm_103a FFMA2 via PTX fma.rn.f32x2)
// ---------------------------------------------------------------------------
__device__ __forceinline__ ull ffma2(ull a, ull b, ull c) {
    ull d;
    asm("fma.rn.f32x2 %0, %1, %2, %3;" : "=l"(d) : "l"(a), "l"(b), "l"(c));
    return d;
}
__device__ __forceinline__ float lo2(ull v) {
    return __uint_as_float((unsigned)(v & 0xFFFFFFFFull));
}
__device__ __forceinline__ float hi2(ull v) {
    return __uint_as_float((unsigned)(v >> 32));
}

// ---------------------------------------------------------------------------
// Fast, overflow-safe tanh: tanh(x) = sign(x)*(1-e)/(1+e), e = 2^(-2|x|log2e)
// ---------------------------------------------------------------------------
__device__ __forceinline__ float fast_tanh(float x) {
    float t = fabsf(x) * -2.8853900817779268f;   // -2*log2(e)*|x|
    float e;
    asm("ex2.approx.f32 %0, %1;" : "=f"(e) : "f"(t));
    float r = __fdividef(1.0f - e, 1.0f + e);
    return copysignf(r, x);
}

// ---------------------------------------------------------------------------
// Wavefront stage kernel. Stage s runs scan-chunk (li, c = s-li) for every
// layer li with c in [0,NC), 64 CTAs per active layer (one per batch elem).
//   Phase 1 (gemm): xp_s[t][j] = dot(W_ih[li][j], prevOut[b,t0+t,:]) + biases
//                   weights in registers (two passes to bound reg pressure).
//   Phase 2 (scan): TC_ recurrent steps; 2 threads per neuron (even/odd k4
//                   blocks, shfl.xor(1) combine); h double-buffered in smem.
// Dependencies scan(l,c) <- {scan(l,c-1), scan(l-1,c)} are both at stage s-1;
// kernel-launch boundaries provide all ordering. Buffer ping-pong
// (layers 0,2,4 -> bufA; 1,3 -> bufB): region (b, chunk c) of layer l is read
// only at stage l+c+1 and next overwritten at stage l+c+2 — safe.
// ---------------------------------------------------------------------------
__global__ void __launch_bounds__(256, 3)
stage_k(int s, const float* __restrict__ x,
        float* __restrict__ bufA, float* __restrict__ bufB,
        const float* __restrict__ W_ih0, const float* __restrict__ W_ih,
        const float* __restrict__ W_hh,
        const float* __restrict__ b_ih, const float* __restrict__ b_hh,
        const float* __restrict__ h0all, float* __restrict__ hst,
        float* __restrict__ hfin)
{
    const int li = blockIdx.x >> 6;        // layer 0..4
    const int b  = blockIdx.x & 63;        // batch element
    const int c  = s - li;                 // chunk index for this layer
    if (c < 0 || c >= NC_) return;         // uniform per CTA (before any sync)
    const int t0 = c * TC_;

    __shared__ __align__(16) float xp_s[TC_ * H_];   // 25600 B
    __shared__ __align__(16) float tile[16 * H_];    //  6400 B
    __shared__ __align__(16) float h_s[2][112];      //   896 B

    const int tid = threadIdx.x;

    float*       obuf = (li & 1) ? bufB : bufA;      // this layer's output
    const float* prev = (li & 1) ? bufA : bufB;      // layer li-1 output
    float* orow = obuf + ((size_t)b * T_ + t0) * H_;

    // ================= Phase 1: GEMM into xp_s =================
    {
        const int jg = tid & 127;
        const int g  = tid >> 7;
        const bool ga = (jg < H_);
        const float bias = ga ? (b_ih[li * H_ + jg] + b_hh[li * H_ + jg]) : 0.0f;

        if (li == 0) {
            // DIN = 10; x rows are 40 B (8B-aligned) -> ull (8B) loads OK
            ull w5[5];
            if (ga) {
                const ull* wp = reinterpret_cast<const ull*>(W_ih0 + (size_t)jg * IN_);
                #pragma unroll
                for (int i = 0; i < 5; i++) w5[i] = wp[i];
            } else {
                #pragma unroll
                for (int i = 0; i < 5; i++) w5[i] = 0ull;
            }
            const float* xrow = x + ((size_t)b * T_ + t0) * IN_;
            for (int tt = 0; tt < TC_; tt += 16) {
                __syncthreads();
                for (int i = tid; i < 16 * IN_; i += 256) tile[i] = xrow[tt * IN_ + i];
                __syncthreads();
                if (ga) {
                    #pragma unroll
                    for (int r = 0; r < 8; r++) {
                        const int tl = 2 * r + g;
                        const ull* xv = reinterpret_cast<const ull*>(tile + tl * IN_);
                        ull a0 = 0ull, a1 = 0ull;
                        a0 = ffma2(w5[0], xv[0], a0);
                        a1 = ffma2(w5[1], xv[1], a1);
                        a0 = ffma2(w5[2], xv[2], a0);
                        a1 = ffma2(w5[3], xv[3], a1);
                        a0 = ffma2(w5[4], xv[4], a0);
                        xp_s[(tt + tl) * H_ + jg] =
                            bias + (lo2(a0) + hi2(a0)) + (lo2(a1) + hi2(a1));
                    }
                }
            }
        } else {
            // DIN = 100; W_ih rows are 400 B (16B-aligned); two weight passes
            const float* Wrow = W_ih + ((size_t)(li - 1) * H_ + jg) * H_;
            const float* arow = prev + ((size_t)b * T_ + t0) * H_;
            for (int tt = 0; tt < TC_; tt += 16) {
                __syncthreads();
                for (int i = tid; i < 16 * H_; i += 256) tile[i] = arow[tt * H_ + i];
                __syncthreads();
                if (ga) {
                    // pass A: k4 blocks 0..12  (floats 0..51)
                    {
                        ulonglong2 wq[13];
                        const ulonglong2* wp = reinterpret_cast<const ulonglong2*>(Wrow);
                        #pragma unroll
                        for (int i = 0; i < 13; i++) wq[i] = wp[i];
                        #pragma unroll
                        for (int r = 0; r < 8; r++) {
                            const int tl = 2 * r + g;
                            const ulonglong2* av =
                                reinterpret_cast<const ulonglong2*>(tile + tl * H_);
                            ull a0 = 0ull, a1 = 0ull, a2 = 0ull, a3 = 0ull;
                            #pragma unroll
                            for (int i = 0; i < 13; i++) {
                                const ulonglong2 hv = av[i];
                                if (i & 1) { a2 = ffma2(wq[i].x, hv.x, a2);
                                             a3 = ffma2(wq[i].y, hv.y, a3); }
                                else       { a0 = ffma2(wq[i].x, hv.x, a0);
                                             a1 = ffma2(wq[i].y, hv.y, a1); }
                            }
                            xp_s[(tt + tl) * H_ + jg] = bias
                                + ((lo2(a0) + hi2(a0)) + (lo2(a1) + hi2(a1)))
                                + ((lo2(a2) + hi2(a2)) + (lo2(a3) + hi2(a3)));
                        }
                    }
                    // pass B: k4 blocks 13..24 (floats 52..99)
                    {
                        ulonglong2 wq[12];
                        const ulonglong2* wp = reinterpret_cast<const ulonglong2*>(Wrow);
                        #pragma unroll
                        for (int i = 0; i < 12; i++) wq[i] = wp[13 + i];
                        #pragma unroll
                        for (int r = 0; r < 8; r++) {
                            const int tl = 2 * r + g;
                            const ulonglong2* av =
                                reinterpret_cast<const ulonglong2*>(tile + tl * H_) + 13;
                            ull a0 = 0ull, a1 = 0ull, a2 = 0ull, a3 = 0ull;
                            #pragma unroll
                            for (int i = 0; i < 12; i++) {
                                const ulonglong2 hv = av[i];
                                if (i & 1) { a2 = ffma2(wq[i].x, hv.x, a2);
                                             a3 = ffma2(wq[i].y, hv.y, a3); }
                                else       { a0 = ffma2(wq[i].x, hv.x, a0);
                                             a1 = ffma2(wq[i].y, hv.y, a1); }
                            }
                            xp_s[(tt + tl) * H_ + jg] +=
                                  ((lo2(a0) + hi2(a0)) + (lo2(a1) + hi2(a1)))
                                + ((lo2(a2) + hi2(a2)) + (lo2(a3) + hi2(a3)));
                        }
                    }
                }
            }
        }
    }
    __syncthreads();

    // ================= Phase 2: recurrent scan =================
    const int j    = tid >> 1;            // neuron 0..127 (active < 100)
    const int half = tid & 1;             // even/odd k4-block half
    const int jr   = (j < H_) ? j : 0;
    const bool ja  = (j < H_);
    const int nb   = 13 - half;           // half 0: 13 blocks, half 1: 12

    // W_hh[li] row j: half h owns k4-blocks 2i+h (each ulonglong2 = 16 B)
    ulonglong2 wq[13];
    #pragma unroll
    for (int i = 0; i < 13; i++) { wq[i].x = 0ull; wq[i].y = 0ull; }
    if (ja) {
        const ulonglong2* wp = reinterpret_cast<const ulonglong2*>(
            W_hh + ((size_t)li * H_ + j) * H_);
        #pragma unroll
        for (int i = 0; i < 13; i++)
            if (i < nb) wq[i] = wp[2 * i + half];
    }

    if (half == 0 && ja) {
        h_s[0][j] = (c == 0) ? h0all[((size_t)li * B_ + b) * H_ + j]
                             : hst[((size_t)li * B_ + b) * H_ + j];
    }
    __syncthreads();

    int cur = 0;
    float th = 0.0f;

    for (int t = 0; t < TC_; t++) {
        const float xpv = xp_s[t * H_ + jr];
        ull a0 = 0ull, a1 = 0ull, a2 = 0ull, a3 = 0ull;
        const ulonglong2* h2 = reinterpret_cast<const ulonglong2*>(h_s[cur]);
        #pragma unroll
        for (int i = 0; i < 13; i++) {
            if (i < nb) {
                const ulonglong2 hv = h2[2 * i + half];
                if (i & 1) { a2 = ffma2(wq[i].x, hv.x, a2);
                             a3 = ffma2(wq[i].y, hv.y, a3); }
                else       { a0 = ffma2(wq[i].x, hv.x, a0);
                             a1 = ffma2(wq[i].y, hv.y, a1); }
            }
        }
        const float part = ((lo2(a0) + hi2(a0)) + (lo2(a1) + hi2(a1)))
                         + ((lo2(a2) + hi2(a2)) + (lo2(a3) + hi2(a3)));
        const float oth = __shfl_xor_sync(0xFFFFFFFFu, part, 1);
        th = fast_tanh(xpv + part + oth);   // both halves compute identical th

        if (half == 0 && ja) {
            h_s[cur ^ 1][j] = th;
            orow[t * H_ + j] = th;          // layer output to global
        }
        __syncthreads();
        cur ^= 1;
    }

    if (half == 0 && ja) {
        hst[((size_t)li * B_ + b) * H_ + j] = th;
        if (c == NC_ - 1) hfin[((size_t)li * B_ + b) * H_ + j] = th;
    }
}

// ---------------------------------------------------------------------------
// Output projection: y[m][o] = sum_k A[m][k]*Wout[o][k] + bout[o]
// (identical structure to the R6 passing version)
// ---------------------------------------------------------------------------
__global__ void __launch_bounds__(256)
proj_k(const float* __restrict__ A, const float* __restrict__ Wout,
       const float* __restrict__ bout, float* __restrict__ y)
{
    __shared__ __align__(16) float Ws[OUT_ * H_];
    __shared__ float bs[OUT_];
    __shared__ __align__(16) float As[16 * H_];

    for (int i = threadIdx.x; i < OUT_ * H_; i += 256) Ws[i] = Wout[i];
    if (threadIdx.x < OUT_) bs[threadIdx.x] = bout[threadIdx.x];

    const int o  = threadIdx.x & 15;
    const int mi = threadIdx.x >> 4;

    const int tilesTotal = M_ / 16;
    for (int tile = blockIdx.x; tile < tilesTotal; tile += gridDim.x) {
        __syncthreads();
        const float* Arow = A + (size_t)tile * 16 * H_;
        for (int i = threadIdx.x; i < 16 * H_; i += 256) As[i] = Arow[i];
        __syncthreads();

        if (o < OUT_) {
            float acc = bs[o];
            #pragma unroll 4
            for (int k = 0; k < H_; k++)
                acc += As[mi * H_ + k] * Ws[o * H_ + k];
            y[(size_t)(tile * 16 + mi) * OUT_ + o] = acc;
        }
    }
}

// ---------------------------------------------------------------------------
// kernel_launch: 37 plain default-stream launches. NO streams, NO events, NO
// attribute calls — only APIs the R6 passing kernel already proved
// capture-safe (kernel<<<>>> + cudaGetSymbolAddress).
// Output: concat( y [B,T,OUT] , h_finals [L,B,H] )
// ---------------------------------------------------------------------------
extern "C" void kernel_launch(void* const* d_in, const int* in_sizes, int n_in,
                              void* d_out, int out_size)
{
    const float* x           = (const float*)d_in[0];
    const float* hidden_prev = (const float*)d_in[1];
    const float* W_ih0       = (const float*)d_in[2];
    const float* W_ih        = (const float*)d_in[3];
    const float* W_hh        = (const float*)d_in[4];
    const float* b_ih        = (const float*)d_in[5];
    const float* b_hh        = (const float*)d_in[6];
    const float* W_out       = (const float*)d_in[7];
    const float* b_out       = (const float*)d_in[8];

    float* out  = (float*)d_out;
    float* y    = out;
    float* hfin = out + (size_t)M_ * OUT_;

    float *bufA, *bufB, *hstBase;
    cudaGetSymbolAddress((void**)&bufA, g_bufA);
    cudaGetSymbolAddress((void**)&bufB, g_bufB);
    cudaGetSymbolAddress((void**)&hstBase, g_hst);

    // Wavefront: stage s executes chunk (l, s-l) for all valid layers at once.
    for (int s = 0; s < NSTAGE; s++) {
        stage_k<<<L_ * B_, 256>>>(s, x, bufA, bufB,
                                  W_ih0, W_ih, W_hh, b_ih, b_hh,
                                  hidden_prev, hstBase, hfin);
    }

    // Layer 4 output lives in bufA (last writer of every chunk region).
    proj_k<<<512, 256>>>(bufA, W_out, b_out, y);
}

// round 10
// speedup vs baseline: 3.2799x; 2.1230x over previous
#include <cuda_runtime.h>
#include <cstddef>

using ull = unsigned long long;

// Problem constants
constexpr int B_   = 64;
constexpr int T_   = 2048;
constexpr int H_   = 100;
constexpr int IN_  = 10;
constexpr int OUT_ = 10;
constexpr int L_   = 5;
constexpr int M_   = B_ * T_;          // 131072 rows
constexpr int BUF_ELEMS = M_ * H_;     // 52.4 MB

constexpr int TC_    = 64;             // timesteps per chunk
constexpr int NC_    = T_ / TC_;       // 32 chunks
constexpr int NSTAGE = NC_ + L_ - 1;   // 36 wavefront stages

// Scratch (device globals: no allocation anywhere)
__device__ float g_bufA[BUF_ELEMS];    // output of layers 0,2,4
__device__ float g_bufB[BUF_ELEMS];    // output of layers 1,3
__device__ float g_xp0[BUF_ELEMS];     // precomputed layer-0 xp (prologue)
__device__ float g_hst[L_ * B_ * H_];  // per-layer hidden-state carry

// ---------------------------------------------------------------------------
// Packed f32x2 helpers (sm_103a FFMA2/FADD2 via PTX)
// ---------------------------------------------------------------------------
__device__ __forceinline__ ull ffma2(ull a, ull b, ull c) {
    ull d;
    asm("fma.rn.f32x2 %0, %1, %2, %3;" : "=l"(d) : "l"(a), "l"(b), "l"(c));
    return d;
}
__device__ __forceinline__ ull addf2(ull a, ull b) {
    ull d;
    asm("add.rn.f32x2 %0, %1, %2;" : "=l"(d) : "l"(a), "l"(b));
    return d;
}
__device__ __forceinline__ float lo2(ull v) {
    return __uint_as_float((unsigned)(v & 0xFFFFFFFFull));
}
__device__ __forceinline__ float hi2(ull v) {
    return __uint_as_float((unsigned)(v >> 32));
}

// ---------------------------------------------------------------------------
// Fast, overflow-safe tanh: tanh(x) = sign(x)*(1-e)/(1+e), e = 2^(-2|x|log2e)
// ---------------------------------------------------------------------------
__device__ __forceinline__ float fast_tanh(float x) {
    float t = fabsf(x) * -2.8853900817779268f;   // -2*log2(e)*|x|
    float e;
    asm("ex2.approx.f32 %0, %1;" : "=f"(e) : "f"(t));
    float r = __fdividef(1.0f - e, 1.0f + e);
    return copysignf(r, x);
}

// ---------------------------------------------------------------------------
// Prologue: layer-0 input GEMM over the ENTIRE sequence (depends only on x).
//   g_xp0[m][c] = sum_k x[m][k]*W_ih0[c][k] + b_ih[0][c] + b_hh[0][c]
// Structure identical to the R6-proven gemm kernel (DIN=10 scalar path).
// ---------------------------------------------------------------------------
__global__ void __launch_bounds__(256)
gemm0_k(const float* __restrict__ A, const float* __restrict__ W,
        const float* __restrict__ b1, const float* __restrict__ b2,
        float* __restrict__ C)
{
    __shared__ __align__(16) float Ws[H_ * IN_];
    __shared__ __align__(16) float As[16 * IN_];

    for (int i = threadIdx.x; i < H_ * IN_; i += 256) Ws[i] = W[i];

    const int c = threadIdx.x & 127;
    const int g = threadIdx.x >> 7;
    const bool act = (c < H_);
    const float bias = act ? (b1[c] + b2[c]) : 0.0f;

    const int tilesTotal = M_ / 16;
    for (int tile = blockIdx.x; tile < tilesTotal; tile += gridDim.x) {
        __syncthreads();
        const float* Arow = A + (size_t)tile * 16 * IN_;
        for (int i = threadIdx.x; i < 16 * IN_; i += 256) As[i] = Arow[i];
        __syncthreads();

        if (act) {
            float acc[8];
            #pragma unroll
            for (int r = 0; r < 8; r++) acc[r] = bias;
            #pragma unroll
            for (int k = 0; k < IN_; k++) {
                const float wv = Ws[c * IN_ + k];
                #pragma unroll
                for (int r = 0; r < 8; r++)
                    acc[r] += wv * As[(g + 2 * r) * IN_ + k];
            }
            #pragma unroll
            for (int r = 0; r < 8; r++)
                C[(size_t)(tile * 16 + g + 2 * r) * H_ + c] = acc[r];
        }
    }
}

// ---------------------------------------------------------------------------
// Wavefront stage kernel. 128 threads, 1 thread per neuron.
// Stage s: CTA (li = bid>>6, b = bid&63) handles chunk c = s-li if valid.
//   Phase 1: li==0 -> float4 copy of precomputed xp0 chunk into smem.
//            li>=1 -> xp_s[t][j] = dot(W_ih[li-1][j], prev[b,t0+t,:]) + bias,
//            full W_ih row (25 x ulonglong2 = 100 regs) held in registers
//            across all 4 tiles; 16-row tiles staged in smem.
//   Phase 2: TC_ recurrent steps; thread j owns neuron j, W_hh row in 100
//            regs, h double-buffered in smem (all h-loads are broadcasts),
//            no shuffles, 4 independent f32x2 accumulator chains.
// Dependencies scan(l,c) <- {scan(l,c-1), scan(l-1,c)} are both at stage s-1;
// kernel-launch boundaries order stages. Ping-pong safety: bufX region (b,c)
// written by layer l at stage l+c, read at l+c+1, next overwritten at l+c+2.
// ---------------------------------------------------------------------------
__global__ void __launch_bounds__(128, 3)
stage_k(int s, const float* __restrict__ xp0,
        float* __restrict__ bufA, float* __restrict__ bufB,
        const float* __restrict__ W_ih, const float* __restrict__ W_hh,
        const float* __restrict__ b_ih, const float* __restrict__ b_hh,
        const float* __restrict__ h0all, float* __restrict__ hst,
        float* __restrict__ hfin)
{
    const int li = blockIdx.x >> 6;        // layer 0..4
    const int b  = blockIdx.x & 63;        // batch element
    const int c  = s - li;                 // chunk index for this layer
    if (c < 0 || c >= NC_) return;         // uniform per CTA (before any sync)
    const int t0 = c * TC_;

    __shared__ __align__(16) float xp_s[TC_ * H_];   // 25600 B
    __shared__ __align__(16) float tile_s[16 * H_];  //  6400 B
    __shared__ __align__(16) float h_s[2][104];      //   832 B

    const int tid = threadIdx.x;
    const int j   = tid;                   // neuron (active if < 100)
    const bool act = (j < H_);
    const int jr  = act ? j : 0;

    float*       obuf = (li & 1) ? bufB : bufA;      // this layer's output
    const float* prev = (li & 1) ? bufA : bufB;      // layer li-1 output
    float* orow = obuf + ((size_t)b * T_ + t0) * H_;

    // ================= Phase 1: xp into smem =================
    if (li == 0) {
        // copy precomputed xp0 chunk (6400 floats, 16B-aligned)
        const float4* src = reinterpret_cast<const float4*>(
            xp0 + ((size_t)b * T_ + t0) * H_);
        float4* dst = reinterpret_cast<float4*>(xp_s);
        for (int i = tid; i < TC_ * H_ / 4; i += 128) dst[i] = src[i];
    } else {
        const float bias = act ? (b_ih[li * H_ + j] + b_hh[li * H_ + j]) : 0.0f;

        // full W_ih row in registers (weights persist across all tiles)
        ulonglong2 wih[25];
        #pragma unroll
        for (int i = 0; i < 25; i++) { wih[i].x = 0ull; wih[i].y = 0ull; }
        if (act) {
            const ulonglong2* wp = reinterpret_cast<const ulonglong2*>(
                W_ih + ((size_t)(li - 1) * H_ + j) * H_);
            #pragma unroll
            for (int i = 0; i < 25; i++) wih[i] = wp[i];
        }

        const float4* arow4 = reinterpret_cast<const float4*>(
            prev + ((size_t)b * T_ + t0) * H_);

        for (int tt = 0; tt < TC_; tt += 16) {
            __syncthreads();   // previous tile consumed
            // stage 16 rows (1600 floats = 400 float4, contiguous, aligned)
            {
                float4* td = reinterpret_cast<float4*>(tile_s);
                const float4* ts = arow4 + tt * (H_ / 4);
                for (int i = tid; i < 16 * H_ / 4; i += 128) td[i] = ts[i];
            }
            __syncthreads();

            if (act) {
                #pragma unroll 4
                for (int r = 0; r < 16; r++) {
                    const ulonglong2* av =
                        reinterpret_cast<const ulonglong2*>(tile_s + r * H_);
                    ull a0 = 0ull, a1 = 0ull, a2 = 0ull, a3 = 0ull;
                    #pragma unroll
                    for (int i = 0; i < 25; i++) {
                        const ulonglong2 hv = av[i];
                        if (i & 1) { a2 = ffma2(wih[i].x, hv.x, a2);
                                     a3 = ffma2(wih[i].y, hv.y, a3); }
                        else       { a0 = ffma2(wih[i].x, hv.x, a0);
                                     a1 = ffma2(wih[i].y, hv.y, a1); }
                    }
                    const ull sall = addf2(addf2(a0, a2), addf2(a1, a3));
                    xp_s[(tt + r) * H_ + j] = bias + lo2(sall) + hi2(sall);
                }
            }
        }
    }

    // ================= Phase 2: recurrent scan =================
    // W_hh row in registers (100 regs), loaded once per stage
    ulonglong2 whh[25];
    #pragma unroll
    for (int i = 0; i < 25; i++) { whh[i].x = 0ull; whh[i].y = 0ull; }
    if (act) {
        const ulonglong2* wp = reinterpret_cast<const ulonglong2*>(
            W_hh + ((size_t)li * H_ + j) * H_);
        #pragma unroll
        for (int i = 0; i < 25; i++) whh[i] = wp[i];

        h_s[0][j] = (c == 0) ? h0all[((size_t)li * B_ + b) * H_ + j]
                             : hst[((size_t)li * B_ + b) * H_ + j];
    }
    __syncthreads();   // xp_s complete + h_s[0] ready

    int cur = 0;
    float th = 0.0f;

    for (int t = 0; t < TC_; t++) {
        const float xpv = xp_s[t * H_ + jr];
        ull a0 = 0ull, a1 = 0ull, a2 = 0ull, a3 = 0ull;
        const ulonglong2* h2 = reinterpret_cast<const ulonglong2*>(h_s[cur]);
        #pragma unroll
        for (int i = 0; i < 25; i++) {          // 25 broadcast LDS.128
            const ulonglong2 hv = h2[i];
            if (i & 1) { a2 = ffma2(whh[i].x, hv.x, a2);
                         a3 = ffma2(whh[i].y, hv.y, a3); }
            else       { a0 = ffma2(whh[i].x, hv.x, a0);
                         a1 = ffma2(whh[i].y, hv.y, a1); }
        }
        const ull sall = addf2(addf2(a0, a2), addf2(a1, a3));
        th = fast_tanh(xpv + lo2(sall) + hi2(sall));

        if (act) {
            h_s[cur ^ 1][j] = th;
            orow[t * H_ + j] = th;              // layer output to global
        }
        __syncthreads();
        cur ^= 1;
    }

    if (act) {
        hst[((size_t)li * B_ + b) * H_ + j] = th;
        if (c == NC_ - 1) hfin[((size_t)li * B_ + b) * H_ + j] = th;
    }
}

// ---------------------------------------------------------------------------
// Output projection: y[m][o] = sum_k A[m][k]*Wout[o][k] + bout[o]
// ---------------------------------------------------------------------------
__global__ void __launch_bounds__(256)
proj_k(const float* __restrict__ A, const float* __restrict__ Wout,
       const float* __restrict__ bout, float* __restrict__ y)
{
    __shared__ __align__(16) float Ws[OUT_ * H_];
    __shared__ float bs[OUT_];
    __shared__ __align__(16) float As[16 * H_];

    for (int i = threadIdx.x; i < OUT_ * H_; i += 256) Ws[i] = Wout[i];
    if (threadIdx.x < OUT_) bs[threadIdx.x] = bout[threadIdx.x];

    const int o  = threadIdx.x & 15;
    const int mi = threadIdx.x >> 4;

    const int tilesTotal = M_ / 16;
    for (int tile = blockIdx.x; tile < tilesTotal; tile += gridDim.x) {
        __syncthreads();
        const float* Arow = A + (size_t)tile * 16 * H_;
        for (int i = threadIdx.x; i < 16 * H_; i += 256) As[i] = Arow[i];
        __syncthreads();

        if (o < OUT_) {
            float acc = bs[o];
            #pragma unroll 4
            for (int k = 0; k < H_; k++)
                acc += As[mi * H_ + k] * Ws[o * H_ + k];
            y[(size_t)(tile * 16 + mi) * OUT_ + o] = acc;
        }
    }
}

// ---------------------------------------------------------------------------
// kernel_launch: 38 plain default-stream launches (prologue + 36 stages +
// proj). NO streams/events/attribute calls — only APIs proven capture-safe.
// Output: concat( y [B,T,OUT] , h_finals [L,B,H] )
// ---------------------------------------------------------------------------
extern "C" void kernel_launch(void* const* d_in, const int* in_sizes, int n_in,
                              void* d_out, int out_size)
{
    const float* x           = (const float*)d_in[0];
    const float* hidden_prev = (const float*)d_in[1];
    const float* W_ih0       = (const float*)d_in[2];
    const float* W_ih        = (const float*)d_in[3];
    const float* W_hh        = (const float*)d_in[4];
    const float* b_ih        = (const float*)d_in[5];
    const float* b_hh        = (const float*)d_in[6];
    const float* W_out       = (const float*)d_in[7];
    const float* b_out       = (const float*)d_in[8];

    float* out  = (float*)d_out;
    float* y    = out;
    float* hfin = out + (size_t)M_ * OUT_;

    float *bufA, *bufB, *xp0, *hstBase;
    cudaGetSymbolAddress((void**)&bufA, g_bufA);
    cudaGetSymbolAddress((void**)&bufB, g_bufB);
    cudaGetSymbolAddress((void**)&xp0,  g_xp0);
    cudaGetSymbolAddress((void**)&hstBase, g_hst);

    // Prologue: layer-0 xp for the whole sequence (depends only on x).
    gemm0_k<<<1024, 256>>>(x, W_ih0, b_ih, b_hh, xp0);

    // Wavefront: stage s executes chunk (l, s-l) for all valid layers at once.
    for (int s = 0; s < NSTAGE; s++) {
        stage_k<<<L_ * B_, 128>>>(s, xp0, bufA, bufB,
                                  W_ih, W_hh, b_ih, b_hh,
                                  hidden_prev, hstBase, hfin);
    }

    // Layer 4 output lives in bufA (last writer of every chunk region).
    proj_k<<<512, 256>>>(bufA, W_out, b_out, y);
}